// round 17
// baseline (speedup 1.0000x reference)
#include <cuda_runtime.h>
#include <cstdint>

// ---------------- problem constants ----------------
#define NBATCH 4
#define NTIME  5
#define GXDIM  400
#define GYDIM  400
#define KTOT   (NBATCH * GXDIM * GYDIM * NTIME)   // 3,200,000 keys

// lookback scan tiling: 625 tiles * 5120 keys == KTOT exactly
#define LB_T    256
#define LB_PK   20
#define LB_TILE (LB_T * LB_PK)                    // 5120
#define LB_NT   (KTOT / LB_TILE)                  // 625

// ---------------- device scratch (no allocations allowed) ----------------
// Phase 1 (accum):   d_acc[key] = [count, sum_x, sum_y, sum_z]
// Phase 2 (scanrank) rewrites present keys in place:
//                    d_acc[key] = [mean_x, mean_y, mean_z, rank_as_float]
__device__ float4       d_acc[KTOT];
__device__ unsigned int d_state[LB_NT];  // lookback tile states: flag<<30 | value
__device__ int          d_tile_ctr;
__device__ int          d_nuniq;

// ---------------- shared helpers ----------------
__device__ __forceinline__ int make_key(float bf, float x, float y, float tf,
                                        int& cx, int& cy) {
    cx = (int)((x + 50.0f) / 0.25f);
    cy = (int)((y + 50.0f) / 0.25f);
    return (((int)bf * GXDIM + cx) * GYDIM + cy) * NTIME + (int)tf;
}

__device__ __forceinline__ void accum_one(float bf, float x, float y, float z, float tf) {
    int cx, cy;
    int key = make_key(bf, x, y, tf, cx, cy);
    asm volatile("red.global.add.v4.f32 [%0], {%1, %2, %3, %4};"
                 :: "l"(&d_acc[key]), "f"(1.0f), "f"(x), "f"(y), "f"(z)
                 : "memory");
}

// after scanrank: d_acc[key] = (mx, my, mz, rankf) — single gather per point
__device__ __forceinline__ float feat_one(float bf, float x, float y, float z,
                                          float inten, float tf, float* r) {
    int cx, cy;
    int key = make_key(bf, x, y, tf, cx, cy);
    float4 m = d_acc[key];
    r[0] = x; r[1] = y; r[2] = z; r[3] = inten;
    r[4] = x - m.x; r[5] = y - m.y; r[6] = z - m.z;
    r[7] = x - ((float)cx * 0.25f + 0.125f + -50.0f);
    r[8] = y - ((float)cy * 0.25f + 0.125f + -50.0f);
    return m.w;   // rank (exact integer in fp32)
}

// ---------------- kernels ----------------
__global__ void k_init(float* __restrict__ out, int N) {
    int tid = blockIdx.x * blockDim.x + threadIdx.x;
    int stride = gridDim.x * blockDim.x;
    const float4 z4 = make_float4(0.f, 0.f, 0.f, 0.f);
    for (int i = tid; i < KTOT; i += stride) d_acc[i] = z4;
    for (int i = tid; i < LB_NT; i += stride) d_state[i] = 0u;
    if (tid == 0) {
        d_tile_ctr = 0;
        d_nuniq = 0;
        float* g = out + (size_t)14 * N;   // grid_size [400,400,1]
        g[0] = 400.0f; g[1] = 400.0f; g[2] = 1.0f;
    }
}

// ---- accumulate: vectorized, 4 pts/thread (6x LDG.128, 4 reds in flight) ----
__global__ void k_accum_v4(const float* __restrict__ pts, int N) {
    int t = blockIdx.x * blockDim.x + threadIdx.x;
    int i0 = t * 4;
    if (i0 >= N) return;
    if (i0 + 3 < N) {
        const float4* p4 = reinterpret_cast<const float4*>(pts) + (size_t)t * 6;
        float4 q0 = p4[0], q1 = p4[1], q2 = p4[2];
        float4 q3 = p4[3], q4 = p4[4], q5 = p4[5];
        accum_one(q0.x, q0.y, q0.z, q0.w, q1.y);   // p0
        accum_one(q1.z, q1.w, q2.x, q2.y, q2.w);   // p1
        accum_one(q3.x, q3.y, q3.z, q3.w, q4.y);   // p2
        accum_one(q4.z, q4.w, q5.x, q5.y, q5.w);   // p3
    } else {
        for (int i = i0; i < N; i++) {
            const float* p = pts + (size_t)i * 6;
            accum_one(p[0], p[1], p[2], p[3], p[5]);
        }
    }
}

// ---- accumulate: scalar fallback ----
__global__ void k_accum_s(const float* __restrict__ pts, int N) {
    int t = blockIdx.x * blockDim.x + threadIdx.x;
    int i0 = t * 4;
    if (i0 >= N) return;
    int e = (i0 + 4 < N) ? i0 + 4 : N;
    for (int i = i0; i < e; i++) {
        const float* p = pts + (size_t)i * 6;
        accum_one(p[0], p[1], p[2], p[3], p[5]);
    }
}

// fused presence-scan + rank + unq decode + IN-PLACE mean/rank rewrite
__global__ void __launch_bounds__(LB_T)
k_scanrank(float* __restrict__ out_unq) {
    __shared__ int s_tile;
    __shared__ int s_wsum[LB_T / 32];
    __shared__ int s_base;

    if (threadIdx.x == 0) s_tile = atomicAdd(&d_tile_ctr, 1);
    __syncthreads();
    const int tile = s_tile;
    const int t = threadIdx.x;
    const int lane = t & 31, warp = t >> 5;
    const int base = tile * LB_TILE + t * LB_PK;   // blocked: ascending key order

    unsigned int flags = 0;
    int s = 0;
#pragma unroll
    for (int j = 0; j < LB_PK; j++) {
        int f = (d_acc[base + j].x > 0.0f) ? 1 : 0;
        flags |= (unsigned)f << j;
        s += f;
    }

    int incl = s;
#pragma unroll
    for (int o = 1; o < 32; o <<= 1) {
        int u = __shfl_up_sync(0xffffffffu, incl, o);
        if (lane >= o) incl += u;
    }
    if (lane == 31) s_wsum[warp] = incl;
    __syncthreads();
    if (warp == 0 && lane < (LB_T / 32)) {
        int v = s_wsum[lane];
        int iv = v;
#pragma unroll
        for (int o = 1; o < (LB_T / 32); o <<= 1) {
            int u = __shfl_up_sync(0xffu, iv, o);
            if (lane >= o) iv += u;
        }
        s_wsum[lane] = iv;
    }
    __syncthreads();
    const int block_total = s_wsum[(LB_T / 32) - 1];
    const int thread_excl = ((warp == 0) ? 0 : s_wsum[warp - 1]) + (incl - s);

    if (t == 0) {
        if (tile == 0) {
            atomicExch(&d_state[0], (2u << 30) | (unsigned)block_total);
            s_base = 0;
        } else {
            atomicExch(&d_state[tile], (1u << 30) | (unsigned)block_total);
            int excl = 0;
            int pt = tile - 1;
            while (true) {
                unsigned v = atomicAdd(&d_state[pt], 0u);
                unsigned fl = v >> 30;
                if (fl == 0u) continue;
                excl += (int)(v & 0x3FFFFFFFu);
                if (fl == 2u) break;
                pt--;
            }
            atomicExch(&d_state[tile], (2u << 30) | (unsigned)(excl + block_total));
            s_base = excl;
        }
        if (tile == LB_NT - 1) {
            unsigned v = atomicAdd(&d_state[tile], 0u);
            d_nuniq = (int)(v & 0x3FFFFFFFu);
        }
    }
    __syncthreads();

    int run = s_base + thread_excl;
#pragma unroll
    for (int j = 0; j < LB_PK; j++) {
        if ((flags >> j) & 1u) {
            int k = base + j;
            // in-place: sums -> (mean, rank)
            float4 v = d_acc[k];
            float rc = 1.0f / v.x;          // count >= 1 for present keys
            d_acc[k] = make_float4(v.y * rc, v.z * rc, v.w * rc, (float)run);

            int tt = k % NTIME;  int k2 = k / NTIME;
            int yy = k2 % GYDIM; k2 /= GYDIM;
            int xx = k2 % GXDIM;
            int bb = k2 / GXDIM;
            reinterpret_cast<float4*>(out_unq)[run] =
                make_float4((float)bb, (float)tt, (float)yy, (float)xx);
            run++;
        }
    }
}

// shared tail: coalesced feature flush for 1024-pt tile (2304 float4s)
__device__ __forceinline__ void feat_tail(float* __restrict__ out, int N,
                                          const float* s, int base_pt, int tid) {
    __syncthreads();
    int cnt = N - base_pt; if (cnt > 1024) cnt = 1024;
    if (cnt == 1024) {
        float4* dst = reinterpret_cast<float4*>(out + (size_t)base_pt * 9);
        const float4* src = reinterpret_cast<const float4*>(s);
#pragma unroll
        for (int j = 0; j < 2304; j += 256) {
            int idx = j + tid;
            if (idx < 2304) dst[idx] = src[idx];
        }
    } else if (cnt > 0) {
        int nf = cnt * 9;
        float* dst = out + (size_t)base_pt * 9;
        for (int j = tid; j < nf; j += 256) dst[j] = s[j];
    }
}

// ---- features: vectorized point loads, fused pad, 4 pts/thread ----
__global__ void __launch_bounds__(256)
k_feat_v4(const float* __restrict__ pts, float* __restrict__ out, int N) {
    __shared__ __align__(16) float s[1024 * 9];   // 36864 B
    const int tid = threadIdx.x;
    const int t = blockIdx.x * 256 + tid;
    const int base_pt = blockIdx.x * 1024;
    const int i0 = t * 4;
    const int nuniq = d_nuniq;

    if (i0 < N) {
        float4* unq4 = reinterpret_cast<float4*>(out + (size_t)9 * N);
        const float4 m1 = make_float4(-1.f, -1.f, -1.f, -1.f);
        if (i0 + 3 < N) {
            const float4* p4 = reinterpret_cast<const float4*>(pts) + (size_t)t * 6;
            float4 q0 = p4[0], q1 = p4[1], q2 = p4[2];
            float4 q3 = p4[3], q4 = p4[4], q5 = p4[5];
            float4 inv;
            inv.x = feat_one(q0.x, q0.y, q0.z, q0.w, q1.x, q1.y, s + (tid * 4 + 0) * 9);
            inv.y = feat_one(q1.z, q1.w, q2.x, q2.y, q2.z, q2.w, s + (tid * 4 + 1) * 9);
            inv.z = feat_one(q3.x, q3.y, q3.z, q3.w, q4.x, q4.y, s + (tid * 4 + 2) * 9);
            inv.w = feat_one(q4.z, q4.w, q5.x, q5.y, q5.z, q5.w, s + (tid * 4 + 3) * 9);
            reinterpret_cast<float4*>(out + (size_t)13 * N)[t] = inv;
#pragma unroll
            for (int j = 0; j < 4; j++)
                if (i0 + j >= nuniq) unq4[i0 + j] = m1;
        } else {
            for (int i = i0; i < N; i++) {
                const float* p = pts + (size_t)i * 6;
                out[(size_t)13 * N + i] =
                    feat_one(p[0], p[1], p[2], p[3], p[4], p[5],
                             s + (tid * 4 + (i - i0)) * 9);
                if (i >= nuniq) unq4[i] = m1;
            }
        }
    }
    feat_tail(out, N, s, base_pt, tid);
}

// ---- features: scalar fallback ----
__global__ void __launch_bounds__(256)
k_feat_s(const float* __restrict__ pts, float* __restrict__ out, int N) {
    __shared__ __align__(16) float s[1024 * 9];
    const int tid = threadIdx.x;
    const int t = blockIdx.x * 256 + tid;
    const int base_pt = blockIdx.x * 1024;
    const int i0 = t * 4;
    const int nuniq = d_nuniq;

    if (i0 < N) {
        float4* unq4 = reinterpret_cast<float4*>(out + (size_t)9 * N);
        const float4 m1 = make_float4(-1.f, -1.f, -1.f, -1.f);
        int e = (i0 + 4 < N) ? i0 + 4 : N;
        for (int i = i0; i < e; i++) {
            const float* p = pts + (size_t)i * 6;
            out[(size_t)13 * N + i] =
                feat_one(p[0], p[1], p[2], p[3], p[4], p[5],
                         s + (tid * 4 + (i - i0)) * 9);
            if (i >= nuniq) unq4[i] = m1;
        }
    }
    feat_tail(out, N, s, base_pt, tid);
}

// ---------------- launch ----------------
extern "C" void kernel_launch(void* const* d_in, const int* in_sizes, int n_in,
                              void* d_out, int out_size) {
    const float* pts = (const float*)d_in[0];
    int N = in_sizes[0] / 6;
    float* out = (float*)d_out;
    float* out_unq = out + (size_t)9 * N;

    int M = (N + 3) / 4;                     // threads handling 4 points each
    int nb4 = (M + 255) / 256;
    bool al16 = (((uintptr_t)pts) & 15u) == 0;   // fixed pointer -> deterministic

    k_init<<<2048, 256>>>(out, N);
    if (al16) k_accum_v4<<<nb4, 256>>>(pts, N);
    else      k_accum_s <<<nb4, 256>>>(pts, N);
    k_scanrank<<<LB_NT, LB_T>>>(out_unq);
    if (al16) k_feat_v4<<<nb4, 256>>>(pts, out, N);
    else      k_feat_s <<<nb4, 256>>>(pts, out, N);
}